// round 16
// baseline (speedup 1.0000x reference)
#include <cuda_runtime.h>
#include <cuda_bf16.h>
#include <math.h>
#include <stdint.h>

#define BATCH 2
#define SEQ   2048
#define DM    1024
#define NH    16
#define HD    64
#define MTOT  (BATCH*SEQ)   // 4096

typedef unsigned short ushort_t;

// ---------------- scratch (__device__ globals; no cudaMalloc allowed) -------
__device__ __nv_bfloat16 g_xh[(size_t)MTOT*DM];   // x  [M,K] hi/lo
__device__ __nv_bfloat16 g_xl[(size_t)MTOT*DM];
__device__ __nv_bfloat16 g_wqh[(size_t)DM*DM];    // W [K,N] hi/lo
__device__ __nv_bfloat16 g_wql[(size_t)DM*DM];
__device__ __nv_bfloat16 g_wkh[(size_t)DM*DM];
__device__ __nv_bfloat16 g_wkl[(size_t)DM*DM];
__device__ __nv_bfloat16 g_wvh[(size_t)DM*DM];
__device__ __nv_bfloat16 g_wvl[(size_t)DM*DM];
__device__ __nv_bfloat16 g_woh[(size_t)DM*DM];
__device__ __nv_bfloat16 g_wol[(size_t)DM*DM];
__device__ __nv_bfloat16 g_qh[(size_t)MTOT*DM];   // [B,H,S,64]
__device__ __nv_bfloat16 g_ql[(size_t)MTOT*DM];
__device__ __nv_bfloat16 g_kh[(size_t)MTOT*DM];
__device__ __nv_bfloat16 g_kl[(size_t)MTOT*DM];
__device__ __nv_bfloat16 g_vh[(size_t)MTOT*DM];
__device__ __nv_bfloat16 g_vl[(size_t)MTOT*DM];
__device__ __nv_bfloat16 g_oh[(size_t)MTOT*DM];   // attn out [B,S,D]
__device__ __nv_bfloat16 g_ol[(size_t)MTOT*DM];

// ---------------- helpers ---------------------------------------------------
__device__ __forceinline__ void splitpack(float x, float y,
                                          unsigned &hi, unsigned &lo) {
    __nv_bfloat16 hx = __float2bfloat16(x);
    __nv_bfloat16 hy = __float2bfloat16(y);
    float lx = x - __bfloat162float(hx);
    float ly = y - __bfloat162float(hy);
    hi = ((unsigned)__bfloat16_as_ushort(hy) << 16) |
          (unsigned)__bfloat16_as_ushort(hx);
    lo = ((unsigned)__bfloat16_as_ushort(__float2bfloat16(ly)) << 16) |
          (unsigned)__bfloat16_as_ushort(__float2bfloat16(lx));
}
__device__ __forceinline__ void ldsm4(unsigned* r, const void* p) {
    unsigned a = (unsigned)__cvta_generic_to_shared(p);
    asm volatile("ldmatrix.sync.aligned.m8n8.x4.shared.b16 {%0,%1,%2,%3}, [%4];"
                 : "=r"(r[0]), "=r"(r[1]), "=r"(r[2]), "=r"(r[3]) : "r"(a));
}
__device__ __forceinline__ void ldsm4t(unsigned* r, const void* p) {
    unsigned a = (unsigned)__cvta_generic_to_shared(p);
    asm volatile("ldmatrix.sync.aligned.m8n8.x4.trans.shared.b16 {%0,%1,%2,%3}, [%4];"
                 : "=r"(r[0]), "=r"(r[1]), "=r"(r[2]), "=r"(r[3]) : "r"(a));
}
__device__ __forceinline__ void mma16816(float* c, const unsigned* a,
                                         const unsigned* b) {
    asm volatile(
        "mma.sync.aligned.m16n8k16.row.col.f32.bf16.bf16.f32 "
        "{%0,%1,%2,%3},{%4,%5,%6,%7},{%8,%9},{%0,%1,%2,%3};"
        : "+f"(c[0]), "+f"(c[1]), "+f"(c[2]), "+f"(c[3])
        : "r"(a[0]), "r"(a[1]), "r"(a[2]), "r"(a[3]), "r"(b[0]), "r"(b[1]));
}
__device__ __forceinline__ void cpa16(void* dst, const void* src) {
    unsigned d = (unsigned)__cvta_generic_to_shared(dst);
    asm volatile("cp.async.cg.shared.global [%0], [%1], 16;" :: "r"(d), "l"(src));
}
__device__ __forceinline__ void cpa_commit() {
    asm volatile("cp.async.commit_group;");
}
template <int N> __device__ __forceinline__ void cpa_wait() {
    asm volatile("cp.async.wait_group %0;" :: "n"(N));
}

// ============================================================================
// prep: all 5 fp32->bf16 hi/lo splits in ONE launch (blockIdx.z selects tensor)
// ============================================================================
struct SplitArgs {
    const float2* src[5];
    unsigned*     hi[5];
    unsigned*     lo[5];
    int           n2[5];
};

__global__ void split_all(SplitArgs a)
{
    const int z = blockIdx.z;
    const float2* __restrict__ src = a.src[z];
    unsigned* __restrict__ hi = a.hi[z];
    unsigned* __restrict__ lo = a.lo[z];
    const int n2 = a.n2[z];
    for (int i = blockIdx.x * blockDim.x + threadIdx.x; i < n2;
         i += gridDim.x * blockDim.x) {
        float2 v = src[i];
        unsigned h, l;
        splitpack(v.x, v.y, h, l);
        hi[i] = h;
        lo[i] = l;
    }
}

// ============================================================================
// Split-bf16 GEMM core (round-5 exact inner loop, 645.6us pedigree).
// 128x128x32, 256 thr, 8 warps (4m x 2n), warp 32x64.
//
// qkv_gemm: ONE launch for Q,K,V projections. grid (24, 32); blockIdx.x>>3
// selects the weight/out set. 768 CTAs -> 2.6 waves instead of 3 partial
// waves, and adjacent CTAs share the A row-block in L2.
// o_gemm: fp32 row-major out (final projection).
// ============================================================================
#define GBK 32
#define AST 40    // halves; 80B stride
#define BST 136   // halves; 272B stride

#define A_PL  (128*AST)
#define A_STG (2*A_PL)
#define B_PL  (GBK*BST)
#define B_STG (2*B_PL)
#define GEMM_SMEM ((2*A_STG + 2*B_STG)*2)   // 75776 bytes

struct QKVArgs {
    const __nv_bfloat16* wh[3];
    const __nv_bfloat16* wl[3];
    const float*         bias[3];
    __nv_bfloat16*       chi[3];
    __nv_bfloat16*       clo[3];
};

// core loop shared by both GEMMs (templated on output mode)
template <int MODE>
__device__ __forceinline__ void gemm_core(
    const __nv_bfloat16* __restrict__ Ah, const __nv_bfloat16* __restrict__ Al,
    const __nv_bfloat16* __restrict__ Wh, const __nv_bfloat16* __restrict__ Wl,
    const float* __restrict__ bias, float scale,
    float* __restrict__ Cf,
    __nv_bfloat16* __restrict__ Chi, __nv_bfloat16* __restrict__ Clo,
    int brow, int bcol, ushort_t* gsm)
{
    ushort_t* Asm = gsm;
    ushort_t* Bsm = gsm + 2 * A_STG;

    const int tid  = threadIdx.x;
    const int lane = tid & 31, warp = tid >> 5;
    const int wm = (warp >> 1) * 32, wn = (warp & 1) * 64;

    const int a_row = tid >> 2, a_c = (tid & 3) * 8;
    const int b_row = tid >> 4, b_c = (tid & 15) * 8;

    auto load_tile = [&](int stage, int kt) {
        #pragma unroll
        for (int p = 0; p < 2; p++) {
            const __nv_bfloat16* Ap = p ? Al : Ah;
            #pragma unroll
            for (int r = 0; r < 2; r++) {
                const int row = a_row + r * 64;
                cpa16(&Asm[stage * A_STG + p * A_PL + row * AST + a_c],
                      Ap + (size_t)(brow + row) * DM + kt + a_c);
            }
        }
        #pragma unroll
        for (int p = 0; p < 2; p++) {
            const __nv_bfloat16* Wp = p ? Wl : Wh;
            #pragma unroll
            for (int r = 0; r < 2; r++) {
                const int row = b_row + r * 16;
                cpa16(&Bsm[stage * B_STG + p * B_PL + row * BST + b_c],
                      Wp + (size_t)(kt + row) * DM + bcol + b_c);
            }
        }
    };

    float acc[2][8][4];
    #pragma unroll
    for (int i = 0; i < 2; i++)
        #pragma unroll
        for (int j = 0; j < 8; j++)
            #pragma unroll
            for (int c = 0; c < 4; c++) acc[i][j][c] = 0.f;

    load_tile(0, 0);  cpa_commit();
    load_tile(1, GBK); cpa_commit();

    const int NIT = DM / GBK;   // 32
    for (int it = 0; it < NIT; it++) {
        if (it < NIT - 1) cpa_wait<1>(); else cpa_wait<0>();
        __syncthreads();

        const int stage = it & 1;
        ushort_t* A0 = Asm + stage * A_STG;
        ushort_t* A1 = A0 + A_PL;
        ushort_t* B0 = Bsm + stage * B_STG;
        ushort_t* B1 = B0 + B_PL;

        #pragma unroll
        for (int ks = 0; ks < 2; ks++) {
            unsigned ah[2][4], al[2][4];
            #pragma unroll
            for (int mi = 0; mi < 2; mi++) {
                const int ar = wm + 16 * mi + (lane & 15);
                const int ac = ks * 16 + ((lane & 16) ? 8 : 0);
                ldsm4(ah[mi], &A0[ar * AST + ac]);
                ldsm4(al[mi], &A1[ar * AST + ac]);
            }
            #pragma unroll
            for (int nq = 0; nq < 4; nq++) {
                const int kr = ks * 16 + (lane & 7) + ((lane & 8) ? 8 : 0);
                const int nc = wn + nq * 16 + ((lane & 16) ? 8 : 0);
                unsigned bh[4], bl[4];
                ldsm4t(bh, &B0[kr * BST + nc]);
                ldsm4t(bl, &B1[kr * BST + nc]);
                #pragma unroll
                for (int mi = 0; mi < 2; mi++) {
                    mma16816(acc[mi][2 * nq],     ah[mi], bh + 0);
                    mma16816(acc[mi][2 * nq + 1], ah[mi], bh + 2);
                    mma16816(acc[mi][2 * nq],     ah[mi], bl + 0);
                    mma16816(acc[mi][2 * nq + 1], ah[mi], bl + 2);
                    mma16816(acc[mi][2 * nq],     al[mi], bh + 0);
                    mma16816(acc[mi][2 * nq + 1], al[mi], bh + 2);
                }
            }
        }
        __syncthreads();
        if (it + 2 < NIT) { load_tile(stage, (it + 2) * GBK); cpa_commit(); }
    }

    const int g = lane >> 2, tg = lane & 3;
    #pragma unroll
    for (int mi = 0; mi < 2; mi++) {
        #pragma unroll
        for (int nf = 0; nf < 8; nf++) {
            const int col = bcol + wn + nf * 8 + 2 * tg;
            const float b0 = bias[col], b1 = bias[col + 1];
            #pragma unroll
            for (int half = 0; half < 2; half++) {
                const int row = brow + wm + 16 * mi + g + 8 * half;
                const float v0 = (acc[mi][nf][2 * half + 0] + b0) * scale;
                const float v1 = (acc[mi][nf][2 * half + 1] + b1) * scale;
                if (MODE == 0) {
                    *(float2*)(Cf + (size_t)row * DM + col) = make_float2(v0, v1);
                } else {
                    const int bb = row >> 11, sq = row & (SEQ - 1);
                    const int hh = col >> 6,  dd = col & (HD - 1);
                    const size_t idx = (((size_t)(bb * NH + hh) * SEQ + sq) * HD + dd);
                    unsigned hi, lo;
                    splitpack(v0, v1, hi, lo);
                    *(unsigned*)(Chi + idx) = hi;
                    *(unsigned*)(Clo + idx) = lo;
                }
            }
        }
    }
}

__global__ void __launch_bounds__(256, 2) qkv_gemm(
    const __nv_bfloat16* __restrict__ Ah, const __nv_bfloat16* __restrict__ Al,
    QKVArgs a)
{
    extern __shared__ ushort_t gsm[];
    const int wsel = blockIdx.x >> 3;                 // 0=Q, 1=K, 2=V
    const int bcol = (blockIdx.x & 7) * 128;
    const int brow = blockIdx.y * 128;
    const float scale = (wsel == 0) ? 0.125f : 1.f;
    gemm_core<1>(Ah, Al, a.wh[wsel], a.wl[wsel], a.bias[wsel], scale,
                 nullptr, a.chi[wsel], a.clo[wsel], brow, bcol, gsm);
}

__global__ void __launch_bounds__(256, 2) o_gemm(
    const __nv_bfloat16* __restrict__ Ah, const __nv_bfloat16* __restrict__ Al,
    const __nv_bfloat16* __restrict__ Wh, const __nv_bfloat16* __restrict__ Wl,
    const float* __restrict__ bias, float* __restrict__ Cf)
{
    extern __shared__ ushort_t gsm[];
    gemm_core<0>(Ah, Al, Wh, Wl, bias, 1.f, Cf, nullptr, nullptr,
                 blockIdx.y * 128, blockIdx.x * 128, gsm);
}

// ============================================================================
// Flash attention (round-5 EXACT — the 645.6us pedigree version)
// ============================================================================
#define QST 72
#define Q_PL   (128*QST)
#define KV_PL  (64*QST)
#define KV_STG (4*KV_PL)
#define KV_BASE (2*Q_PL)
#define ATTN_SMEM ((2*Q_PL + 2*KV_STG)*2)   // 110592 bytes

__global__ void __launch_bounds__(128, 2) mma_attn(
    const __nv_bfloat16* __restrict__ Qh, const __nv_bfloat16* __restrict__ Ql,
    const __nv_bfloat16* __restrict__ Kh, const __nv_bfloat16* __restrict__ Kl,
    const __nv_bfloat16* __restrict__ Vh, const __nv_bfloat16* __restrict__ Vl,
    __nv_bfloat16* __restrict__ Ohi, __nv_bfloat16* __restrict__ Olo)
{
    extern __shared__ ushort_t sm[];

    const int tid = threadIdx.x, lane = tid & 31, warp = tid >> 5;
    const int q0 = blockIdx.x * 128;
    const int h  = blockIdx.y,  b = blockIdx.z;
    const size_t hoff = (size_t)(b * NH + h) * SEQ * HD;

    const __nv_bfloat16* kvp[4] = { Kh + hoff, Kl + hoff, Vh + hoff, Vl + hoff };

    const int lr = tid >> 3, lc = (tid & 7) * 8;

    auto load_kv = [&](int stage, int kv0) {
        #pragma unroll
        for (int k = 0; k < 16; k++) {
            const int p   = k >> 2;
            const int row = lr + (k & 3) * 16;
            cpa16(&sm[KV_BASE + stage * KV_STG + p * KV_PL + row * QST + lc],
                  kvp[p] + (size_t)(kv0 + row) * HD + lc);
        }
    };

    {
        const __nv_bfloat16* qp[2] = { Qh + hoff, Ql + hoff };
        #pragma unroll
        for (int k = 0; k < 16; k++) {
            const int p   = k >> 3;
            const int row = lr + (k & 7) * 16;
            cpa16(&sm[p * Q_PL + row * QST + lc],
                  qp[p] + (size_t)(q0 + row) * HD + lc);
        }
    }
    load_kv(0, 0); cpa_commit();
    load_kv(1, 64); cpa_commit();

    const int g = lane >> 2, tg = lane & 3;
    float m[2][2], l[2][2], o[2][8][4];
    #pragma unroll
    for (int mi = 0; mi < 2; mi++) {
        m[mi][0] = -INFINITY; m[mi][1] = -INFINITY;
        l[mi][0] = 0.f;       l[mi][1] = 0.f;
        #pragma unroll
        for (int i = 0; i < 8; i++)
            #pragma unroll
            for (int c = 0; c < 4; c++) o[mi][i][c] = 0.f;
    }

    const int NIT = SEQ / 64;   // 32
    for (int it = 0; it < NIT; it++) {
        if (it < NIT - 1) cpa_wait<1>(); else cpa_wait<0>();
        __syncthreads();

        const int stage = it & 1;
        ushort_t* Ksh = sm + KV_BASE + stage * KV_STG;
        ushort_t* Ksl = Ksh + KV_PL;
        ushort_t* Vsh = Ksl + KV_PL;
        ushort_t* Vsl = Vsh + KV_PL;

        float s[2][8][4];
        #pragma unroll
        for (int mi = 0; mi < 2; mi++)
            #pragma unroll
            for (int i = 0; i < 8; i++)
                #pragma unroll
                for (int c = 0; c < 4; c++) s[mi][i][c] = 0.f;

        #pragma unroll
        for (int ks = 0; ks < 4; ks++) {
            unsigned ah[2][4], al[2][4];
            #pragma unroll
            for (int mi = 0; mi < 2; mi++) {
                const int ar = warp * 32 + 16 * mi + (lane & 15);
                const int ac = ks * 16 + ((lane & 16) ? 8 : 0);
                ldsm4(ah[mi], &sm[0 * Q_PL + ar * QST + ac]);
                ldsm4(al[mi], &sm[1 * Q_PL + ar * QST + ac]);
            }
            #pragma unroll
            for (int nq = 0; nq < 4; nq++) {
                const int srow = nq * 16 + (lane & 7) + ((lane & 16) ? 8 : 0);
                const int dcol = ks * 16 + ((lane & 8) ? 8 : 0);
                unsigned bh[4], bl[4];
                ldsm4(bh, &Ksh[srow * QST + dcol]);
                ldsm4(bl, &Ksl[srow * QST + dcol]);
                #pragma unroll
                for (int mi = 0; mi < 2; mi++) {
                    mma16816(s[mi][2 * nq],     ah[mi], bh + 0);
                    mma16816(s[mi][2 * nq + 1], ah[mi], bh + 2);
                    mma16816(s[mi][2 * nq],     ah[mi], bl + 0);
                    mma16816(s[mi][2 * nq + 1], ah[mi], bl + 2);
                    mma16816(s[mi][2 * nq],     al[mi], bh + 0);
                    mma16816(s[mi][2 * nq + 1], al[mi], bh + 2);
                }
            }
        }

        unsigned ph[2][8][2], pl[2][8][2];
        #pragma unroll
        for (int mi = 0; mi < 2; mi++) {
            float mx0 = -INFINITY, mx1 = -INFINITY;
            #pragma unroll
            for (int i = 0; i < 8; i++) {
                mx0 = fmaxf(mx0, fmaxf(s[mi][i][0], s[mi][i][1]));
                mx1 = fmaxf(mx1, fmaxf(s[mi][i][2], s[mi][i][3]));
            }
            mx0 = fmaxf(mx0, __shfl_xor_sync(0xffffffffu, mx0, 1));
            mx0 = fmaxf(mx0, __shfl_xor_sync(0xffffffffu, mx0, 2));
            mx1 = fmaxf(mx1, __shfl_xor_sync(0xffffffffu, mx1, 1));
            mx1 = fmaxf(mx1, __shfl_xor_sync(0xffffffffu, mx1, 2));
            const float mn0 = fmaxf(m[mi][0], mx0), mn1 = fmaxf(m[mi][1], mx1);
            const float c0 = __expf(m[mi][0] - mn0), c1 = __expf(m[mi][1] - mn1);
            m[mi][0] = mn0; m[mi][1] = mn1;
            float rs0 = 0.f, rs1 = 0.f;
            #pragma unroll
            for (int i = 0; i < 8; i++) {
                s[mi][i][0] = __expf(s[mi][i][0] - mn0);
                s[mi][i][1] = __expf(s[mi][i][1] - mn0);
                s[mi][i][2] = __expf(s[mi][i][2] - mn1);
                s[mi][i][3] = __expf(s[mi][i][3] - mn1);
                rs0 += s[mi][i][0] + s[mi][i][1];
                rs1 += s[mi][i][2] + s[mi][i][3];
            }
            rs0 += __shfl_xor_sync(0xffffffffu, rs0, 1);
            rs0 += __shfl_xor_sync(0xffffffffu, rs0, 2);
            rs1 += __shfl_xor_sync(0xffffffffu, rs1, 1);
            rs1 += __shfl_xor_sync(0xffffffffu, rs1, 2);
            l[mi][0] = l[mi][0] * c0 + rs0;
            l[mi][1] = l[mi][1] * c1 + rs1;
            #pragma unroll
            for (int i = 0; i < 8; i++) {
                o[mi][i][0] *= c0; o[mi][i][1] *= c0;
                o[mi][i][2] *= c1; o[mi][i][3] *= c1;
                splitpack(s[mi][i][0], s[mi][i][1], ph[mi][i][0], pl[mi][i][0]);
                splitpack(s[mi][i][2], s[mi][i][3], ph[mi][i][1], pl[mi][i][1]);
            }
        }

        #pragma unroll
        for (int kss = 0; kss < 4; kss++) {
            unsigned a2h[2][4], a2l[2][4];
            #pragma unroll
            for (int mi = 0; mi < 2; mi++) {
                a2h[mi][0] = ph[mi][2 * kss][0];     a2h[mi][1] = ph[mi][2 * kss][1];
                a2h[mi][2] = ph[mi][2 * kss + 1][0]; a2h[mi][3] = ph[mi][2 * kss + 1][1];
                a2l[mi][0] = pl[mi][2 * kss][0];     a2l[mi][1] = pl[mi][2 * kss][1];
                a2l[mi][2] = pl[mi][2 * kss + 1][0]; a2l[mi][3] = pl[mi][2 * kss + 1][1];
            }
            #pragma unroll
            for (int nq = 0; nq < 4; nq++) {
                const int srow = kss * 16 + (lane & 7) + ((lane & 8) ? 8 : 0);
                const int dcol = nq * 16 + ((lane & 16) ? 8 : 0);
                unsigned bh[4], bl[4];
                ldsm4t(bh, &Vsh[srow * QST + dcol]);
                ldsm4t(bl, &Vsl[srow * QST + dcol]);
                #pragma unroll
                for (int mi = 0; mi < 2; mi++) {
                    mma16816(o[mi][2 * nq],     a2h[mi], bh + 0);
                    mma16816(o[mi][2 * nq + 1], a2h[mi], bh + 2);
                    mma16816(o[mi][2 * nq],     a2h[mi], bl + 0);
                    mma16816(o[mi][2 * nq + 1], a2h[mi], bl + 2);
                    mma16816(o[mi][2 * nq],     a2l[mi], bh + 0);
                    mma16816(o[mi][2 * nq + 1], a2l[mi], bh + 2);
                }
            }
        }
        __syncthreads();
        if (it + 2 < NIT) { load_kv(stage, (it + 2) * 64); cpa_commit(); }
    }

    #pragma unroll
    for (int mi = 0; mi < 2; mi++) {
        const float i0 = 1.f / l[mi][0], i1 = 1.f / l[mi][1];
        #pragma unroll
        for (int nf = 0; nf < 8; nf++) {
            const int d  = h * HD + nf * 8 + 2 * tg;
            const int r0 = q0 + warp * 32 + 16 * mi + g;
            unsigned hi, lo;
            splitpack(o[mi][nf][0] * i0, o[mi][nf][1] * i0, hi, lo);
            *(unsigned*)(Ohi + (size_t)(b * SEQ + r0) * DM + d) = hi;
            *(unsigned*)(Olo + (size_t)(b * SEQ + r0) * DM + d) = lo;
            splitpack(o[mi][nf][2] * i1, o[mi][nf][3] * i1, hi, lo);
            *(unsigned*)(Ohi + (size_t)(b * SEQ + r0 + 8) * DM + d) = hi;
            *(unsigned*)(Olo + (size_t)(b * SEQ + r0 + 8) * DM + d) = lo;
        }
    }
}

// ============================================================================
// launch: split_all(0), qkv_gemm(1), attn(2), o_gemm(3)
// ============================================================================
extern "C" void kernel_launch(void* const* d_in, const int* in_sizes, int n_in,
                              void* d_out, int out_size)
{
    const float* x  = (const float*)d_in[0];
    const float* Wq = (const float*)d_in[1];
    const float* bq = (const float*)d_in[2];
    const float* Wk = (const float*)d_in[3];
    const float* bk = (const float*)d_in[4];
    const float* Wv = (const float*)d_in[5];
    const float* bv = (const float*)d_in[6];
    const float* Wo = (const float*)d_in[7];
    const float* bo = (const float*)d_in[8];
    float* out = (float*)d_out;

    void *xh, *xl, *wqh, *wql, *wkh, *wkl, *wvh, *wvl, *woh, *wol;
    void *qh, *ql, *kh, *kl, *vh, *vl, *oh, *ol;
    cudaGetSymbolAddress(&xh, g_xh);   cudaGetSymbolAddress(&xl, g_xl);
    cudaGetSymbolAddress(&wqh, g_wqh); cudaGetSymbolAddress(&wql, g_wql);
    cudaGetSymbolAddress(&wkh, g_wkh); cudaGetSymbolAddress(&wkl, g_wkl);
    cudaGetSymbolAddress(&wvh, g_wvh); cudaGetSymbolAddress(&wvl, g_wvl);
    cudaGetSymbolAddress(&woh, g_woh); cudaGetSymbolAddress(&wol, g_wol);
    cudaGetSymbolAddress(&qh, g_qh);   cudaGetSymbolAddress(&ql, g_ql);
    cudaGetSymbolAddress(&kh, g_kh);   cudaGetSymbolAddress(&kl, g_kl);
    cudaGetSymbolAddress(&vh, g_vh);   cudaGetSymbolAddress(&vl, g_vl);
    cudaGetSymbolAddress(&oh, g_oh);   cudaGetSymbolAddress(&ol, g_ol);

    // prep: one fused launch for all 5 splits
    SplitArgs sa;
    sa.src[0] = (const float2*)x;  sa.hi[0] = (unsigned*)xh;  sa.lo[0] = (unsigned*)xl;  sa.n2[0] = MTOT*DM/2;
    sa.src[1] = (const float2*)Wq; sa.hi[1] = (unsigned*)wqh; sa.lo[1] = (unsigned*)wql; sa.n2[1] = DM*DM/2;
    sa.src[2] = (const float2*)Wk; sa.hi[2] = (unsigned*)wkh; sa.lo[2] = (unsigned*)wkl; sa.n2[2] = DM*DM/2;
    sa.src[3] = (const float2*)Wv; sa.hi[3] = (unsigned*)wvh; sa.lo[3] = (unsigned*)wvl; sa.n2[3] = DM*DM/2;
    sa.src[4] = (const float2*)Wo; sa.hi[4] = (unsigned*)woh; sa.lo[4] = (unsigned*)wol; sa.n2[4] = DM*DM/2;
    split_all<<<dim3(128, 1, 5), 256>>>(sa);

    cudaFuncSetAttribute(qkv_gemm, cudaFuncAttributeMaxDynamicSharedMemorySize, GEMM_SMEM);
    cudaFuncSetAttribute(o_gemm,   cudaFuncAttributeMaxDynamicSharedMemorySize, GEMM_SMEM);
    cudaFuncSetAttribute(mma_attn, cudaFuncAttributeMaxDynamicSharedMemorySize, ATTN_SMEM);

    // fused QKV: grid (24, 32) = 768 CTAs
    QKVArgs qa;
    qa.wh[0] = (const __nv_bfloat16*)wqh; qa.wl[0] = (const __nv_bfloat16*)wql;
    qa.wh[1] = (const __nv_bfloat16*)wkh; qa.wl[1] = (const __nv_bfloat16*)wkl;
    qa.wh[2] = (const __nv_bfloat16*)wvh; qa.wl[2] = (const __nv_bfloat16*)wvl;
    qa.bias[0] = bq; qa.bias[1] = bk; qa.bias[2] = bv;
    qa.chi[0] = (__nv_bfloat16*)qh; qa.clo[0] = (__nv_bfloat16*)ql;
    qa.chi[1] = (__nv_bfloat16*)kh; qa.clo[1] = (__nv_bfloat16*)kl;
    qa.chi[2] = (__nv_bfloat16*)vh; qa.clo[2] = (__nv_bfloat16*)vl;
    qkv_gemm<<<dim3(24, MTOT / 128), 256, GEMM_SMEM>>>(
        (const __nv_bfloat16*)xh, (const __nv_bfloat16*)xl, qa);

    mma_attn<<<dim3(SEQ / 128, NH, BATCH), 128, ATTN_SMEM>>>(
        (const __nv_bfloat16*)qh, (const __nv_bfloat16*)ql,
        (const __nv_bfloat16*)kh, (const __nv_bfloat16*)kl,
        (const __nv_bfloat16*)vh, (const __nv_bfloat16*)vl,
        (__nv_bfloat16*)oh, (__nv_bfloat16*)ol);

    o_gemm<<<dim3(DM / 128, MTOT / 128), 256, GEMM_SMEM>>>(
        (const __nv_bfloat16*)oh, (const __nv_bfloat16*)ol,
        (const __nv_bfloat16*)woh, (const __nv_bfloat16*)wol,
        bo, out);
}

// round 17
// speedup vs baseline: 1.5063x; 1.5063x over previous
#include <cuda_runtime.h>
#include <cuda_bf16.h>
#include <math.h>
#include <stdint.h>

#define BATCH 2
#define SEQ   2048
#define DM    1024
#define NH    16
#define HD    64
#define MTOT  (BATCH*SEQ)   // 4096

typedef unsigned short ushort_t;

// ---------------- scratch (__device__ globals; no cudaMalloc allowed) -------
__device__ __nv_bfloat16 g_xh[(size_t)MTOT*DM];   // x  [M,K] hi/lo
__device__ __nv_bfloat16 g_xl[(size_t)MTOT*DM];
__device__ __nv_bfloat16 g_wqh[(size_t)DM*DM];    // W [K,N] hi/lo
__device__ __nv_bfloat16 g_wql[(size_t)DM*DM];
__device__ __nv_bfloat16 g_wkh[(size_t)DM*DM];
__device__ __nv_bfloat16 g_wkl[(size_t)DM*DM];
__device__ __nv_bfloat16 g_wvh[(size_t)DM*DM];
__device__ __nv_bfloat16 g_wvl[(size_t)DM*DM];
__device__ __nv_bfloat16 g_woh[(size_t)DM*DM];
__device__ __nv_bfloat16 g_wol[(size_t)DM*DM];
__device__ __nv_bfloat16 g_qh[(size_t)MTOT*DM];   // [B,H,S,64]
__device__ __nv_bfloat16 g_ql[(size_t)MTOT*DM];
__device__ __nv_bfloat16 g_kh[(size_t)MTOT*DM];
__device__ __nv_bfloat16 g_kl[(size_t)MTOT*DM];
__device__ __nv_bfloat16 g_vh[(size_t)MTOT*DM];
__device__ __nv_bfloat16 g_vl[(size_t)MTOT*DM];
__device__ __nv_bfloat16 g_oh[(size_t)MTOT*DM];   // attn out [B,S,D]
__device__ __nv_bfloat16 g_ol[(size_t)MTOT*DM];

// ---------------- helpers ---------------------------------------------------
__device__ __forceinline__ void splitpack(float x, float y,
                                          unsigned &hi, unsigned &lo) {
    __nv_bfloat16 hx = __float2bfloat16(x);
    __nv_bfloat16 hy = __float2bfloat16(y);
    float lx = x - __bfloat162float(hx);
    float ly = y - __bfloat162float(hy);
    hi = ((unsigned)__bfloat16_as_ushort(hy) << 16) |
          (unsigned)__bfloat16_as_ushort(hx);
    lo = ((unsigned)__bfloat16_as_ushort(__float2bfloat16(ly)) << 16) |
          (unsigned)__bfloat16_as_ushort(__float2bfloat16(lx));
}
__device__ __forceinline__ void ldsm4(unsigned* r, const void* p) {
    unsigned a = (unsigned)__cvta_generic_to_shared(p);
    asm volatile("ldmatrix.sync.aligned.m8n8.x4.shared.b16 {%0,%1,%2,%3}, [%4];"
                 : "=r"(r[0]), "=r"(r[1]), "=r"(r[2]), "=r"(r[3]) : "r"(a));
}
__device__ __forceinline__ void ldsm4t(unsigned* r, const void* p) {
    unsigned a = (unsigned)__cvta_generic_to_shared(p);
    asm volatile("ldmatrix.sync.aligned.m8n8.x4.trans.shared.b16 {%0,%1,%2,%3}, [%4];"
                 : "=r"(r[0]), "=r"(r[1]), "=r"(r[2]), "=r"(r[3]) : "r"(a));
}
__device__ __forceinline__ void mma16816(float* c, const unsigned* a,
                                         const unsigned* b) {
    asm volatile(
        "mma.sync.aligned.m16n8k16.row.col.f32.bf16.bf16.f32 "
        "{%0,%1,%2,%3},{%4,%5,%6,%7},{%8,%9},{%0,%1,%2,%3};"
        : "+f"(c[0]), "+f"(c[1]), "+f"(c[2]), "+f"(c[3])
        : "r"(a[0]), "r"(a[1]), "r"(a[2]), "r"(a[3]), "r"(b[0]), "r"(b[1]));
}
__device__ __forceinline__ void cpa16(void* dst, const void* src) {
    unsigned d = (unsigned)__cvta_generic_to_shared(dst);
    asm volatile("cp.async.cg.shared.global [%0], [%1], 16;" :: "r"(d), "l"(src));
}
__device__ __forceinline__ void cpa_commit() {
    asm volatile("cp.async.commit_group;");
}
template <int N> __device__ __forceinline__ void cpa_wait() {
    asm volatile("cp.async.wait_group %0;" :: "n"(N));
}

// ============================================================================
// prep: all 5 fp32->bf16 hi/lo splits in ONE launch (blockIdx.z selects tensor)
// ============================================================================
struct SplitArgs {
    const float2* src[5];
    unsigned*     hi[5];
    unsigned*     lo[5];
    int           n2[5];
};

__global__ void split_all(SplitArgs a)
{
    const int z = blockIdx.z;
    const float2* __restrict__ src = a.src[z];
    unsigned* __restrict__ hi = a.hi[z];
    unsigned* __restrict__ lo = a.lo[z];
    const int n2 = a.n2[z];
    for (int i = blockIdx.x * blockDim.x + threadIdx.x; i < n2;
         i += gridDim.x * blockDim.x) {
        float2 v = src[i];
        unsigned h, l;
        splitpack(v.x, v.y, h, l);
        hi[i] = h;
        lo[i] = l;
    }
}

// ============================================================================
// Split-bf16 GEMM (round-5 EXACT, 645.6us pedigree).
// C = A@W + bias (3-term split), 128x128x32, 256 thr, 8 warps, warp 32x64.
// MODE 0: fp32 row-major out. MODE 1: bf16 hi/lo [B,H,S,64] out, scaled.
// ============================================================================
#define GBK 32
#define AST 40    // halves; 80B stride
#define BST 136   // halves; 272B stride

#define A_PL  (128*AST)
#define A_STG (2*A_PL)
#define B_PL  (GBK*BST)
#define B_STG (2*B_PL)
#define GEMM_SMEM ((2*A_STG + 2*B_STG)*2)   // 75776 bytes

template <int MODE>
__global__ void __launch_bounds__(256, 2) mma_gemm(
    const __nv_bfloat16* __restrict__ Ah, const __nv_bfloat16* __restrict__ Al,
    const __nv_bfloat16* __restrict__ Wh, const __nv_bfloat16* __restrict__ Wl,
    const float* __restrict__ bias, float scale,
    float* __restrict__ Cf,
    __nv_bfloat16* __restrict__ Chi, __nv_bfloat16* __restrict__ Clo)
{
    extern __shared__ ushort_t gsm[];
    ushort_t* Asm = gsm;
    ushort_t* Bsm = gsm + 2 * A_STG;

    const int tid  = threadIdx.x;
    const int lane = tid & 31, warp = tid >> 5;
    const int wm = (warp >> 1) * 32, wn = (warp & 1) * 64;
    const int brow = blockIdx.y * 128, bcol = blockIdx.x * 128;

    const int a_row = tid >> 2, a_c = (tid & 3) * 8;
    const int b_row = tid >> 4, b_c = (tid & 15) * 8;

    auto load_tile = [&](int stage, int kt) {
        #pragma unroll
        for (int p = 0; p < 2; p++) {
            const __nv_bfloat16* Ap = p ? Al : Ah;
            #pragma unroll
            for (int r = 0; r < 2; r++) {
                const int row = a_row + r * 64;
                cpa16(&Asm[stage * A_STG + p * A_PL + row * AST + a_c],
                      Ap + (size_t)(brow + row) * DM + kt + a_c);
            }
        }
        #pragma unroll
        for (int p = 0; p < 2; p++) {
            const __nv_bfloat16* Wp = p ? Wl : Wh;
            #pragma unroll
            for (int r = 0; r < 2; r++) {
                const int row = b_row + r * 16;
                cpa16(&Bsm[stage * B_STG + p * B_PL + row * BST + b_c],
                      Wp + (size_t)(kt + row) * DM + bcol + b_c);
            }
        }
    };

    float acc[2][8][4];
    #pragma unroll
    for (int i = 0; i < 2; i++)
        #pragma unroll
        for (int j = 0; j < 8; j++)
            #pragma unroll
            for (int c = 0; c < 4; c++) acc[i][j][c] = 0.f;

    load_tile(0, 0);  cpa_commit();
    load_tile(1, GBK); cpa_commit();

    const int NIT = DM / GBK;   // 32
    for (int it = 0; it < NIT; it++) {
        if (it < NIT - 1) cpa_wait<1>(); else cpa_wait<0>();
        __syncthreads();

        const int stage = it & 1;
        ushort_t* A0 = Asm + stage * A_STG;
        ushort_t* A1 = A0 + A_PL;
        ushort_t* B0 = Bsm + stage * B_STG;
        ushort_t* B1 = B0 + B_PL;

        #pragma unroll
        for (int ks = 0; ks < 2; ks++) {
            unsigned ah[2][4], al[2][4];
            #pragma unroll
            for (int mi = 0; mi < 2; mi++) {
                const int ar = wm + 16 * mi + (lane & 15);
                const int ac = ks * 16 + ((lane & 16) ? 8 : 0);
                ldsm4(ah[mi], &A0[ar * AST + ac]);
                ldsm4(al[mi], &A1[ar * AST + ac]);
            }
            #pragma unroll
            for (int nq = 0; nq < 4; nq++) {
                const int kr = ks * 16 + (lane & 7) + ((lane & 8) ? 8 : 0);
                const int nc = wn + nq * 16 + ((lane & 16) ? 8 : 0);
                unsigned bh[4], bl[4];
                ldsm4t(bh, &B0[kr * BST + nc]);
                ldsm4t(bl, &B1[kr * BST + nc]);
                #pragma unroll
                for (int mi = 0; mi < 2; mi++) {
                    mma16816(acc[mi][2 * nq],     ah[mi], bh + 0);
                    mma16816(acc[mi][2 * nq + 1], ah[mi], bh + 2);
                    mma16816(acc[mi][2 * nq],     ah[mi], bl + 0);
                    mma16816(acc[mi][2 * nq + 1], ah[mi], bl + 2);
                    mma16816(acc[mi][2 * nq],     al[mi], bh + 0);
                    mma16816(acc[mi][2 * nq + 1], al[mi], bh + 2);
                }
            }
        }
        __syncthreads();
        if (it + 2 < NIT) { load_tile(stage, (it + 2) * GBK); cpa_commit(); }
    }

    const int g = lane >> 2, tg = lane & 3;
    #pragma unroll
    for (int mi = 0; mi < 2; mi++) {
        #pragma unroll
        for (int nf = 0; nf < 8; nf++) {
            const int col = bcol + wn + nf * 8 + 2 * tg;
            const float b0 = bias[col], b1 = bias[col + 1];
            #pragma unroll
            for (int half = 0; half < 2; half++) {
                const int row = brow + wm + 16 * mi + g + 8 * half;
                const float v0 = (acc[mi][nf][2 * half + 0] + b0) * scale;
                const float v1 = (acc[mi][nf][2 * half + 1] + b1) * scale;
                if (MODE == 0) {
                    *(float2*)(Cf + (size_t)row * DM + col) = make_float2(v0, v1);
                } else {
                    const int bb = row >> 11, sq = row & (SEQ - 1);
                    const int hh = col >> 6,  dd = col & (HD - 1);
                    const size_t idx = (((size_t)(bb * NH + hh) * SEQ + sq) * HD + dd);
                    unsigned hi, lo;
                    splitpack(v0, v1, hi, lo);
                    *(unsigned*)(Chi + idx) = hi;
                    *(unsigned*)(Clo + idx) = lo;
                }
            }
        }
    }
}

// ============================================================================
// Flash attention (round-5 EXACT — 645.6us pedigree)
// ============================================================================
#define QST 72
#define Q_PL   (128*QST)
#define KV_PL  (64*QST)
#define KV_STG (4*KV_PL)
#define KV_BASE (2*Q_PL)
#define ATTN_SMEM ((2*Q_PL + 2*KV_STG)*2)   // 110592 bytes

__global__ void __launch_bounds__(128, 2) mma_attn(
    const __nv_bfloat16* __restrict__ Qh, const __nv_bfloat16* __restrict__ Ql,
    const __nv_bfloat16* __restrict__ Kh, const __nv_bfloat16* __restrict__ Kl,
    const __nv_bfloat16* __restrict__ Vh, const __nv_bfloat16* __restrict__ Vl,
    __nv_bfloat16* __restrict__ Ohi, __nv_bfloat16* __restrict__ Olo)
{
    extern __shared__ ushort_t sm[];

    const int tid = threadIdx.x, lane = tid & 31, warp = tid >> 5;
    const int q0 = blockIdx.x * 128;
    const int h  = blockIdx.y,  b = blockIdx.z;
    const size_t hoff = (size_t)(b * NH + h) * SEQ * HD;

    const __nv_bfloat16* kvp[4] = { Kh + hoff, Kl + hoff, Vh + hoff, Vl + hoff };

    const int lr = tid >> 3, lc = (tid & 7) * 8;

    auto load_kv = [&](int stage, int kv0) {
        #pragma unroll
        for (int k = 0; k < 16; k++) {
            const int p   = k >> 2;
            const int row = lr + (k & 3) * 16;
            cpa16(&sm[KV_BASE + stage * KV_STG + p * KV_PL + row * QST + lc],
                  kvp[p] + (size_t)(kv0 + row) * HD + lc);
        }
    };

    {
        const __nv_bfloat16* qp[2] = { Qh + hoff, Ql + hoff };
        #pragma unroll
        for (int k = 0; k < 16; k++) {
            const int p   = k >> 3;
            const int row = lr + (k & 7) * 16;
            cpa16(&sm[p * Q_PL + row * QST + lc],
                  qp[p] + (size_t)(q0 + row) * HD + lc);
        }
    }
    load_kv(0, 0); cpa_commit();
    load_kv(1, 64); cpa_commit();

    const int g = lane >> 2, tg = lane & 3;
    float m[2][2], l[2][2], o[2][8][4];
    #pragma unroll
    for (int mi = 0; mi < 2; mi++) {
        m[mi][0] = -INFINITY; m[mi][1] = -INFINITY;
        l[mi][0] = 0.f;       l[mi][1] = 0.f;
        #pragma unroll
        for (int i = 0; i < 8; i++)
            #pragma unroll
            for (int c = 0; c < 4; c++) o[mi][i][c] = 0.f;
    }

    const int NIT = SEQ / 64;   // 32
    for (int it = 0; it < NIT; it++) {
        if (it < NIT - 1) cpa_wait<1>(); else cpa_wait<0>();
        __syncthreads();

        const int stage = it & 1;
        ushort_t* Ksh = sm + KV_BASE + stage * KV_STG;
        ushort_t* Ksl = Ksh + KV_PL;
        ushort_t* Vsh = Ksl + KV_PL;
        ushort_t* Vsl = Vsh + KV_PL;

        float s[2][8][4];
        #pragma unroll
        for (int mi = 0; mi < 2; mi++)
            #pragma unroll
            for (int i = 0; i < 8; i++)
                #pragma unroll
                for (int c = 0; c < 4; c++) s[mi][i][c] = 0.f;

        #pragma unroll
        for (int ks = 0; ks < 4; ks++) {
            unsigned ah[2][4], al[2][4];
            #pragma unroll
            for (int mi = 0; mi < 2; mi++) {
                const int ar = warp * 32 + 16 * mi + (lane & 15);
                const int ac = ks * 16 + ((lane & 16) ? 8 : 0);
                ldsm4(ah[mi], &sm[0 * Q_PL + ar * QST + ac]);
                ldsm4(al[mi], &sm[1 * Q_PL + ar * QST + ac]);
            }
            #pragma unroll
            for (int nq = 0; nq < 4; nq++) {
                const int srow = nq * 16 + (lane & 7) + ((lane & 16) ? 8 : 0);
                const int dcol = ks * 16 + ((lane & 8) ? 8 : 0);
                unsigned bh[4], bl[4];
                ldsm4(bh, &Ksh[srow * QST + dcol]);
                ldsm4(bl, &Ksl[srow * QST + dcol]);
                #pragma unroll
                for (int mi = 0; mi < 2; mi++) {
                    mma16816(s[mi][2 * nq],     ah[mi], bh + 0);
                    mma16816(s[mi][2 * nq + 1], ah[mi], bh + 2);
                    mma16816(s[mi][2 * nq],     ah[mi], bl + 0);
                    mma16816(s[mi][2 * nq + 1], ah[mi], bl + 2);
                    mma16816(s[mi][2 * nq],     al[mi], bh + 0);
                    mma16816(s[mi][2 * nq + 1], al[mi], bh + 2);
                }
            }
        }

        unsigned ph[2][8][2], pl[2][8][2];
        #pragma unroll
        for (int mi = 0; mi < 2; mi++) {
            float mx0 = -INFINITY, mx1 = -INFINITY;
            #pragma unroll
            for (int i = 0; i < 8; i++) {
                mx0 = fmaxf(mx0, fmaxf(s[mi][i][0], s[mi][i][1]));
                mx1 = fmaxf(mx1, fmaxf(s[mi][i][2], s[mi][i][3]));
            }
            mx0 = fmaxf(mx0, __shfl_xor_sync(0xffffffffu, mx0, 1));
            mx0 = fmaxf(mx0, __shfl_xor_sync(0xffffffffu, mx0, 2));
            mx1 = fmaxf(mx1, __shfl_xor_sync(0xffffffffu, mx1, 1));
            mx1 = fmaxf(mx1, __shfl_xor_sync(0xffffffffu, mx1, 2));
            const float mn0 = fmaxf(m[mi][0], mx0), mn1 = fmaxf(m[mi][1], mx1);
            const float c0 = __expf(m[mi][0] - mn0), c1 = __expf(m[mi][1] - mn1);
            m[mi][0] = mn0; m[mi][1] = mn1;
            float rs0 = 0.f, rs1 = 0.f;
            #pragma unroll
            for (int i = 0; i < 8; i++) {
                s[mi][i][0] = __expf(s[mi][i][0] - mn0);
                s[mi][i][1] = __expf(s[mi][i][1] - mn0);
                s[mi][i][2] = __expf(s[mi][i][2] - mn1);
                s[mi][i][3] = __expf(s[mi][i][3] - mn1);
                rs0 += s[mi][i][0] + s[mi][i][1];
                rs1 += s[mi][i][2] + s[mi][i][3];
            }
            rs0 += __shfl_xor_sync(0xffffffffu, rs0, 1);
            rs0 += __shfl_xor_sync(0xffffffffu, rs0, 2);
            rs1 += __shfl_xor_sync(0xffffffffu, rs1, 1);
            rs1 += __shfl_xor_sync(0xffffffffu, rs1, 2);
            l[mi][0] = l[mi][0] * c0 + rs0;
            l[mi][1] = l[mi][1] * c1 + rs1;
            #pragma unroll
            for (int i = 0; i < 8; i++) {
                o[mi][i][0] *= c0; o[mi][i][1] *= c0;
                o[mi][i][2] *= c1; o[mi][i][3] *= c1;
                splitpack(s[mi][i][0], s[mi][i][1], ph[mi][i][0], pl[mi][i][0]);
                splitpack(s[mi][i][2], s[mi][i][3], ph[mi][i][1], pl[mi][i][1]);
            }
        }

        #pragma unroll
        for (int kss = 0; kss < 4; kss++) {
            unsigned a2h[2][4], a2l[2][4];
            #pragma unroll
            for (int mi = 0; mi < 2; mi++) {
                a2h[mi][0] = ph[mi][2 * kss][0];     a2h[mi][1] = ph[mi][2 * kss][1];
                a2h[mi][2] = ph[mi][2 * kss + 1][0]; a2h[mi][3] = ph[mi][2 * kss + 1][1];
                a2l[mi][0] = pl[mi][2 * kss][0];     a2l[mi][1] = pl[mi][2 * kss][1];
                a2l[mi][2] = pl[mi][2 * kss + 1][0]; a2l[mi][3] = pl[mi][2 * kss + 1][1];
            }
            #pragma unroll
            for (int nq = 0; nq < 4; nq++) {
                const int srow = kss * 16 + (lane & 7) + ((lane & 8) ? 8 : 0);
                const int dcol = nq * 16 + ((lane & 16) ? 8 : 0);
                unsigned bh[4], bl[4];
                ldsm4t(bh, &Vsh[srow * QST + dcol]);
                ldsm4t(bl, &Vsl[srow * QST + dcol]);
                #pragma unroll
                for (int mi = 0; mi < 2; mi++) {
                    mma16816(o[mi][2 * nq],     a2h[mi], bh + 0);
                    mma16816(o[mi][2 * nq + 1], a2h[mi], bh + 2);
                    mma16816(o[mi][2 * nq],     a2h[mi], bl + 0);
                    mma16816(o[mi][2 * nq + 1], a2h[mi], bl + 2);
                    mma16816(o[mi][2 * nq],     a2l[mi], bh + 0);
                    mma16816(o[mi][2 * nq + 1], a2l[mi], bh + 2);
                }
            }
        }
        __syncthreads();
        if (it + 2 < NIT) { load_kv(stage, (it + 2) * 64); cpa_commit(); }
    }

    #pragma unroll
    for (int mi = 0; mi < 2; mi++) {
        const float i0 = 1.f / l[mi][0], i1 = 1.f / l[mi][1];
        #pragma unroll
        for (int nf = 0; nf < 8; nf++) {
            const int d  = h * HD + nf * 8 + 2 * tg;
            const int r0 = q0 + warp * 32 + 16 * mi + g;
            unsigned hi, lo;
            splitpack(o[mi][nf][0] * i0, o[mi][nf][1] * i0, hi, lo);
            *(unsigned*)(Ohi + (size_t)(b * SEQ + r0) * DM + d) = hi;
            *(unsigned*)(Olo + (size_t)(b * SEQ + r0) * DM + d) = lo;
            splitpack(o[mi][nf][2] * i1, o[mi][nf][3] * i1, hi, lo);
            *(unsigned*)(Ohi + (size_t)(b * SEQ + r0 + 8) * DM + d) = hi;
            *(unsigned*)(Olo + (size_t)(b * SEQ + r0 + 8) * DM + d) = lo;
        }
    }
}

// ============================================================================
// launch (round-5 structure; only prep is fused)
// ============================================================================
extern "C" void kernel_launch(void* const* d_in, const int* in_sizes, int n_in,
                              void* d_out, int out_size)
{
    const float* x  = (const float*)d_in[0];
    const float* Wq = (const float*)d_in[1];
    const float* bq = (const float*)d_in[2];
    const float* Wk = (const float*)d_in[3];
    const float* bk = (const float*)d_in[4];
    const float* Wv = (const float*)d_in[5];
    const float* bv = (const float*)d_in[6];
    const float* Wo = (const float*)d_in[7];
    const float* bo = (const float*)d_in[8];
    float* out = (float*)d_out;

    void *xh, *xl, *wqh, *wql, *wkh, *wkl, *wvh, *wvl, *woh, *wol;
    void *qh, *ql, *kh, *kl, *vh, *vl, *oh, *ol;
    cudaGetSymbolAddress(&xh, g_xh);   cudaGetSymbolAddress(&xl, g_xl);
    cudaGetSymbolAddress(&wqh, g_wqh); cudaGetSymbolAddress(&wql, g_wql);
    cudaGetSymbolAddress(&wkh, g_wkh); cudaGetSymbolAddress(&wkl, g_wkl);
    cudaGetSymbolAddress(&wvh, g_wvh); cudaGetSymbolAddress(&wvl, g_wvl);
    cudaGetSymbolAddress(&woh, g_woh); cudaGetSymbolAddress(&wol, g_wol);
    cudaGetSymbolAddress(&qh, g_qh);   cudaGetSymbolAddress(&ql, g_ql);
    cudaGetSymbolAddress(&kh, g_kh);   cudaGetSymbolAddress(&kl, g_kl);
    cudaGetSymbolAddress(&vh, g_vh);   cudaGetSymbolAddress(&vl, g_vl);
    cudaGetSymbolAddress(&oh, g_oh);   cudaGetSymbolAddress(&ol, g_ol);

    // prep: one fused launch for all 5 splits (same math as round-5 split_kernel)
    SplitArgs sa;
    sa.src[0] = (const float2*)x;  sa.hi[0] = (unsigned*)xh;  sa.lo[0] = (unsigned*)xl;  sa.n2[0] = MTOT*DM/2;
    sa.src[1] = (const float2*)Wq; sa.hi[1] = (unsigned*)wqh; sa.lo[1] = (unsigned*)wql; sa.n2[1] = DM*DM/2;
    sa.src[2] = (const float2*)Wk; sa.hi[2] = (unsigned*)wkh; sa.lo[2] = (unsigned*)wkl; sa.n2[2] = DM*DM/2;
    sa.src[3] = (const float2*)Wv; sa.hi[3] = (unsigned*)wvh; sa.lo[3] = (unsigned*)wvl; sa.n2[3] = DM*DM/2;
    sa.src[4] = (const float2*)Wo; sa.hi[4] = (unsigned*)woh; sa.lo[4] = (unsigned*)wol; sa.n2[4] = DM*DM/2;
    split_all<<<dim3(128, 1, 5), 256>>>(sa);

    cudaFuncSetAttribute(mma_gemm<0>, cudaFuncAttributeMaxDynamicSharedMemorySize, GEMM_SMEM);
    cudaFuncSetAttribute(mma_gemm<1>, cudaFuncAttributeMaxDynamicSharedMemorySize, GEMM_SMEM);
    cudaFuncSetAttribute(mma_attn, cudaFuncAttributeMaxDynamicSharedMemorySize, ATTN_SMEM);

    dim3 gg(DM / 128, MTOT / 128);   // (8, 32)
    mma_gemm<1><<<gg, 256, GEMM_SMEM>>>(
        (const __nv_bfloat16*)xh, (const __nv_bfloat16*)xl,
        (const __nv_bfloat16*)wqh, (const __nv_bfloat16*)wql,
        bq, 0.125f, nullptr, (__nv_bfloat16*)qh, (__nv_bfloat16*)ql);
    mma_gemm<1><<<gg, 256, GEMM_SMEM>>>(
        (const __nv_bfloat16*)xh, (const __nv_bfloat16*)xl,
        (const __nv_bfloat16*)wkh, (const __nv_bfloat16*)wkl,
        bk, 1.f, nullptr, (__nv_bfloat16*)kh, (__nv_bfloat16*)kl);
    mma_gemm<1><<<gg, 256, GEMM_SMEM>>>(
        (const __nv_bfloat16*)xh, (const __nv_bfloat16*)xl,
        (const __nv_bfloat16*)wvh, (const __nv_bfloat16*)wvl,
        bv, 1.f, nullptr, (__nv_bfloat16*)vh, (__nv_bfloat16*)vl);

    mma_attn<<<dim3(SEQ / 128, NH, BATCH), 128, ATTN_SMEM>>>(
        (const __nv_bfloat16*)qh, (const __nv_bfloat16*)ql,
        (const __nv_bfloat16*)kh, (const __nv_bfloat16*)kl,
        (const __nv_bfloat16*)vh, (const __nv_bfloat16*)vl,
        (__nv_bfloat16*)oh, (__nv_bfloat16*)ol);

    mma_gemm<0><<<gg, 256, GEMM_SMEM>>>(
        (const __nv_bfloat16*)oh, (const __nv_bfloat16*)ol,
        (const __nv_bfloat16*)woh, (const __nv_bfloat16*)wol,
        bo, 1.f, out, nullptr, nullptr);
}